// round 10
// baseline (speedup 1.0000x reference)
#include <cuda_runtime.h>
#include <math.h>

#define W 4096
#define S4 1024           // float4 per row
#define NKMAX 1024
#define SHARP 50.0f
#define MAXWIN 64
#define CGRID 256         // corr blocks
#define CK (NKMAX/CGRID)  // keys per corr block (4)

// ---------------- device scratch (no allocations allowed) ----------------
__device__ float2 g_mix[W];       // noisy_mix
__device__ float2 g_tw[W];        // twiddle table e^{i 2pi m / W}
__device__ float  g_corr[NKMAX];
__device__ unsigned g_t2;         // corr block ticket   (monotonic across replays)
__device__ unsigned g_t3;         // out block ticket    (monotonic across replays)
__device__ unsigned g_done;       // softmax completion epoch (monotonic)
__device__ int    g_nwin;         // number of nonzero-attention winners
__device__ int    g_winn[MAXWIN]; // winner key indices (sorted ascending)
__device__ float  g_wina[MAXWIN]; // winner attention weights

// block-wide complex reduction (256 threads, 8 warps). Caller syncs before reuse.
__device__ __forceinline__ float2 block_reduce_c(float re, float im, float2* sred) {
#pragma unroll
    for (int off = 16; off; off >>= 1) {
        re += __shfl_xor_sync(0xffffffffu, re, off);
        im += __shfl_xor_sync(0xffffffffu, im, off);
    }
    int wid = threadIdx.x >> 5;
    if ((threadIdx.x & 31) == 0) sred[wid] = make_float2(re, im);
    __syncthreads();
    float2 acc = sred[0];
#pragma unroll
    for (int i = 1; i < 8; i++) { acc.x += sred[i].x; acc.y += sred[i].y; }
    return acc;
}

// ---------------- phase 1: noisy_mix[w] = sum_s holo*conj(cue) ----------------
__global__ __launch_bounds__(256) void k_mix(
    const float4* __restrict__ hr, const float4* __restrict__ hi,
    const float4* __restrict__ cr, const float4* __restrict__ ci)
{
    int row = blockIdx.x;
    int t   = threadIdx.x;
    if (row < 16) {   // side job: twiddle table
        int i = row * 256 + t;
        float s, c;
        sincospif((float)i * (1.0f / 2048.0f), &s, &c);  // i/2048 exact in fp32
        g_tw[i] = make_float2(c, s);
    }
    int base = row * S4;
    float re = 0.f, im = 0.f;
#pragma unroll
    for (int k = 0; k < 4; k++) {
        int i = base + t + k * 256;
        float4 a = hr[i];            // retain in L2 for k_out
        float4 b = hi[i];
        float4 c = __ldcs(&cr[i]);   // streaming
        float4 d = __ldcs(&ci[i]);
        re += a.x * c.x + b.x * d.x;  im += b.x * c.x - a.x * d.x;
        re += a.y * c.y + b.y * d.y;  im += b.y * c.y - a.y * d.y;
        re += a.z * c.z + b.z * d.z;  im += b.z * c.z - a.z * d.z;
        re += a.w * c.w + b.w * d.w;  im += b.w * c.w - a.w * d.w;
    }
    __shared__ float2 sred[8];
    float2 acc = block_reduce_c(re, im, sred);
    if (t == 0) g_mix[row] = acc;
}

// ------ phase 2: correlations (phasor recurrence) + last-block softmax ------
__global__ __launch_bounds__(256) void k_corr(const int* __restrict__ nkp) {
    cudaTriggerProgrammaticLaunchCompletion();   // release k_out's PDL launch
    cudaGridDependencySynchronize();             // k_mix fully done (no early trigger)

    int t   = threadIdx.x;
    int cid = blockIdx.x;
    int nk  = *nkp;
    __shared__ float2 sred[8];

    // key f: twiddle at w advances by rot = e^{i 2pi f*256/W} per 256-step chunk
    float tre[CK], tim[CK], rre[CK], rim[CK], are[CK], aim[CK];
#pragma unroll
    for (int kk = 0; kk < CK; kk++) {
        unsigned f = (unsigned)(cid * CK + kk) + 1u;
        float2 t0 = g_tw[(f * (unsigned)t) & 4095u];   // exact init
        float2 r0 = g_tw[(f << 8) & 4095u];            // exact rotation const
        tre[kk] = t0.x; tim[kk] = t0.y;
        rre[kk] = r0.x; rim[kk] = r0.y;
        are[kk] = 0.f;  aim[kk] = 0.f;
    }
#pragma unroll
    for (int ch = 0; ch < 16; ch++) {
        float2 m = __ldg(&g_mix[t + 256 * ch]);
#pragma unroll
        for (int kk = 0; kk < CK; kk++) {
            are[kk] += tre[kk] * m.x - tim[kk] * m.y;
            aim[kk] += tre[kk] * m.y + tim[kk] * m.x;
            float nr = tre[kk] * rre[kk] - tim[kk] * rim[kk];
            tim[kk]  = tre[kk] * rim[kk] + tim[kk] * rre[kk];
            tre[kk]  = nr;
        }
    }
#pragma unroll
    for (int kk = 0; kk < CK; kk++) {
        float2 acc = block_reduce_c(are[kk], aim[kk], sred);
        int n = cid * CK + kk;
        if (t == 0 && n < nk) g_corr[n] = sqrtf(acc.x * acc.x + acc.y * acc.y);
        __syncthreads();
    }
    __threadfence();

    // last-arriving block (monotonic ticket) does softmax + winner compaction
    __shared__ unsigned sT2;
    if (t == 0) sT2 = atomicAdd(&g_t2, 1u);
    __syncthreads();
    if ((sT2 & (CGRID - 1u)) != (CGRID - 1u)) return;
    __threadfence();

    __shared__ float sredf[8];
    __shared__ float slog[NKMAX];
    __shared__ int   s_cnt;
    if (t == 0) s_cnt = 0;

    float l[4], mx = -INFINITY;
#pragma unroll
    for (int j = 0; j < 4; j++) {
        int n = t + 256 * j;
        float c = (n < nk) ? __ldcg(&g_corr[n]) : 0.f;
        l[j] = (n < nk) ? c * SHARP : -INFINITY;
        mx = fmaxf(mx, l[j]);
    }
#pragma unroll
    for (int off = 16; off; off >>= 1) mx = fmaxf(mx, __shfl_xor_sync(0xffffffffu, mx, off));
    if ((t & 31) == 0) sredf[t >> 5] = mx;
    __syncthreads();
    float bm = sredf[0];
#pragma unroll
    for (int i = 1; i < 8; i++) bm = fmaxf(bm, sredf[i]);
    __syncthreads();

    float e[4], s = 0.f;
#pragma unroll
    for (int j = 0; j < 4; j++) {
        int n = t + 256 * j;
        e[j] = (n < nk) ? expf(l[j] - bm) : 0.f;
        slog[t + 256 * j] = e[j];
        s += e[j];
    }
#pragma unroll
    for (int off = 16; off; off >>= 1) s += __shfl_xor_sync(0xffffffffu, s, off);
    if ((t & 31) == 0) sredf[t >> 5] = s;
    __syncthreads();
    float bs = sredf[0];
#pragma unroll
    for (int i = 1; i < 8; i++) bs += sredf[i];
    __syncthreads();

#pragma unroll
    for (int j = 0; j < 4; j++) {
        int n = t + 256 * j;
        float a = slog[n] / bs;
        if (a != 0.f && n < nk) {
            int slot = atomicAdd(&s_cnt, 1);
            if (slot < MAXWIN) { g_winn[slot] = n; g_wina[slot] = a; }
        }
    }
    __syncthreads();
    if (t == 0) {
        int m = s_cnt < MAXWIN ? s_cnt : MAXWIN;
        for (int i = 1; i < m; i++) {           // sort ascending by n
            int   kn = g_winn[i];
            float ka = g_wina[i];
            int j = i - 1;
            while (j >= 0 && g_winn[j] > kn) {
                g_winn[j + 1] = g_winn[j]; g_wina[j + 1] = g_wina[j]; j--;
            }
            g_winn[j + 1] = kn; g_wina[j + 1] = ka;
        }
        g_nwin = m;
        __threadfence();
        atomicAdd(&g_done, 1u);                 // publish epoch
    }
}

// ---------------- phase 3: out = holo * clean_key[:,None] ----------------
// PDL-launched concurrently with k_corr: prefetch full row into registers,
// spin on the softmax epoch, then multiply + store.
__global__ __launch_bounds__(256) void k_out(
    const float4* __restrict__ hr, const float4* __restrict__ hi,
    float4* __restrict__ out)
{
    cudaGridDependencySynchronize();            // k_corr has triggered (at entry)

    int t    = threadIdx.x;
    int row  = (W - 1) - blockIdx.x;            // reverse: hit L2-hot tail of k_mix
    int base = row * S4;
    int i0 = base + t, i1 = i0 + 256, i2 = i0 + 512, i3 = i0 + 768;

    // prefetch entire row (overlaps with k_corr's compute under PDL)
    float4 a0 = hr[i0], b0 = hi[i0];
    float4 a1 = hr[i1], b1 = hi[i1];
    float4 a2 = hr[i2], b2 = hi[i2];
    float4 a3 = hr[i3], b3 = hi[i3];

    // replay index (monotonic ticket) + spin for this replay's softmax epoch
    __shared__ unsigned sR;
    if (t == 0) sR = atomicAdd(&g_t3, 1u) >> 12;    // / 4096 blocks per launch
    __syncthreads();
    unsigned rep = sR;
    if (t == 0) {
        volatile unsigned* p = &g_done;
        while (*p <= rep) __nanosleep(128);
    }
    __syncthreads();
    __threadfence();

    // clean_key[row] from compacted winners (one-hot in practice)
    int m = g_nwin;
    const float F = (float)(6.283185307179586 / 4096.0);  // fl(2*pi/W)
    float fw = (float)row;
    float ckre = 0.f, ckim = 0.f;
    for (int i = 0; i < m; i++) {
        int   n = g_winn[i];
        float a = g_wina[i];
        float freq = (float)(n + 1) * F;   // reference rounding order
        float ph   = freq * fw;
        float sn, cs;
        sincosf(ph, &sn, &cs);
        ckre = fmaf(a, cs, ckre);
        ckim = fmaf(a, sn, ckim);
    }

#define EMIT(ai, bi, idx)                                              \
    {                                                                  \
        float4 o0, o1;                                                 \
        o0.x = ai.x * ckre - bi.x * ckim;  o1.x = ai.x * ckim + bi.x * ckre; \
        o0.y = ai.y * ckre - bi.y * ckim;  o1.y = ai.y * ckim + bi.y * ckre; \
        o0.z = ai.z * ckre - bi.z * ckim;  o1.z = ai.z * ckim + bi.z * ckre; \
        o0.w = ai.w * ckre - bi.w * ckim;  o1.w = ai.w * ckim + bi.w * ckre; \
        __stcs(&out[idx],            o0);                              \
        __stcs(&out[idx + W * S4],   o1);                              \
    }
    EMIT(a0, b0, i0)
    EMIT(a1, b1, i1)
    EMIT(a2, b2, i2)
    EMIT(a3, b3, i3)
#undef EMIT
}

// ---------------- launcher ----------------
extern "C" void kernel_launch(void* const* d_in, const int* in_sizes, int n_in,
                              void* d_out, int out_size) {
    const float4* hr = (const float4*)d_in[0];
    const float4* hi = (const float4*)d_in[1];
    const float4* cr = (const float4*)d_in[2];
    const float4* ci = (const float4*)d_in[3];
    const int*    nk = (const int*)d_in[4];

    k_mix<<<W, 256>>>(hr, hi, cr, ci);

    cudaLaunchAttribute at[1];
    at[0].id = cudaLaunchAttributeProgrammaticStreamSerialization;
    at[0].val.programmaticStreamSerializationAllowed = 1;

    cudaLaunchConfig_t c1 = {};
    c1.gridDim  = dim3(CGRID);
    c1.blockDim = dim3(256);
    c1.stream   = 0;
    c1.attrs    = at;
    c1.numAttrs = 1;
    cudaLaunchKernelEx(&c1, k_corr, nk);

    cudaLaunchConfig_t c2 = {};
    c2.gridDim  = dim3(W);
    c2.blockDim = dim3(256);
    c2.stream   = 0;
    c2.attrs    = at;
    c2.numAttrs = 1;
    cudaLaunchKernelEx(&c2, k_out, hr, hi, (float4*)d_out);
}